// round 2
// baseline (speedup 1.0000x reference)
#include <cuda_runtime.h>
#include <math.h>
#include <stdint.h>

#define Bv 32
#define Tv 64
#define Sv 64
#define Ev 512
#define Hv 512
#define D2v 1024
#define Vv 32000
#define BH (Bv*Hv)              // 16384
#define ATT_SCALE 0.0441941738241592f   // 1/sqrt(512)

// ---------------- scratch (device globals; no allocations allowed) ----------
__device__ float g_x[Bv*Tv*Ev];          // embedded inputs [b][t][e]
__device__ float g_h[2][2*BH];           // double-buffered hidden state [buf][dir][b][u]
__device__ float g_c[2*BH];              // cell state (in-place)
__device__ float g_hh[2*BH];             // hhat state
__device__ float g_gpart[3][2*Bv*4*Hv]; // gate GEMM partials (K-split 3)
__device__ float g_kpart[2][2*Bv*D2v];  // attention key partials (K-split 2)
__device__ float g_hcat[2*Bv*(Hv+D2v)]; // [h, ct] concat per (dir,b)
__device__ float g_hpart[6][2*BH];      // hhat GEMM partials (K-split 6)
__device__ float g_outf[Tv*BH];          // forward hhat sequence [t][b][u]
__device__ float g_outb[Tv*BH];          // backward hhat sequence (scan order)
__device__ float g_feat[Bv*Tv*2*Hv];     // packed features for fc

// ---------------- embedding gather ----------------
__global__ void embed_kernel(const float* __restrict__ emb, const int* __restrict__ trg)
{
    int i = blockIdx.x*blockDim.x + threadIdx.x;
    if (i >= Bv*Tv*Ev) return;
    int e = i & 511;
    int bt = i >> 9;
    g_x[i] = emb[(long)trg[bt]*Ev + e];
}

// ---------------- init states ----------------
__global__ void init_kernel(const float* __restrict__ feed_init, const float* __restrict__ hid_init)
{
    int i = blockIdx.x*blockDim.x + threadIdx.x;
    if (i >= 2*BH) return;
    int u = i & 511;
    int dir = i >> 14;
    g_h[0][i] = hid_init[dir*1024 + u];
    g_c[i]    = hid_init[dir*1024 + 512 + u];
    g_hh[i]   = feed_init[dir*512 + u];
}

// ---------------- gates GEMM: g += xin@Wih^T + h@Whh^T (K-split z=0..2) -----
__global__ __launch_bounds__(256) void gates_kernel(int t,
    const float* __restrict__ fWih, const float* __restrict__ fWhh,
    const float* __restrict__ bWih, const float* __restrict__ bWhh)
{
    int n0  = blockIdx.x * 64;
    int dir = blockIdx.y;
    int z   = blockIdx.z;
    int tsel = dir ? (Tv-1-t) : t;
    const float* Wih = dir ? bWih : fWih;
    const float* Whh = dir ? bWhh : fWhh;

    __shared__ float As[32][17];
    __shared__ float Ws[64][17];
    int tid = threadIdx.x;
    int ty = tid >> 4, tx = tid & 15;
    float acc[2][4] = {};

    for (int k0 = 0; k0 < 512; k0 += 16) {
        for (int i = tid; i < 512; i += 256) {
            int m = i >> 4, kc = i & 15;
            int k = k0 + kc;
            float v;
            if (z == 0)      v = g_x[(m*Tv + tsel)*Ev + k];
            else if (z == 1) v = g_hh[dir*BH + m*Hv + k];
            else             v = g_h[t&1][dir*BH + m*Hv + k];
            As[m][kc] = v;
        }
        for (int i = tid; i < 1024; i += 256) {
            int r = i >> 4, kc = i & 15;
            int k = k0 + kc;
            int col = n0 + r;
            Ws[r][kc] = (z < 2) ? Wih[col*1024 + z*512 + k] : Whh[col*512 + k];
        }
        __syncthreads();
        #pragma unroll
        for (int kc = 0; kc < 16; kc++) {
            float a0 = As[ty][kc], a1 = As[ty+16][kc];
            #pragma unroll
            for (int j = 0; j < 4; j++) {
                float w = Ws[tx*4+j][kc];
                acc[0][j] = fmaf(a0, w, acc[0][j]);
                acc[1][j] = fmaf(a1, w, acc[1][j]);
            }
        }
        __syncthreads();
    }
    float* out = g_gpart[z] + dir*Bv*4*Hv;
    #pragma unroll
    for (int j = 0; j < 4; j++) {
        out[ty*2048      + n0 + tx*4 + j] = acc[0][j];
        out[(ty+16)*2048 + n0 + tx*4 + j] = acc[1][j];
    }
}

// ---------------- LSTM pointwise update ----------------
__global__ void lstm_kernel(int t, const float* __restrict__ mask,
    const float* __restrict__ fbih, const float* __restrict__ fbhh,
    const float* __restrict__ bbih, const float* __restrict__ bbhh)
{
    int i = blockIdx.x*blockDim.x + threadIdx.x;
    if (i >= 2*BH) return;
    int u = i & 511;
    int b = (i >> 9) & 31;
    int dir = i >> 14;
    const float* bih = dir ? bbih : fbih;
    const float* bhh = dir ? bbhh : fbhh;
    int base = (dir*Bv + b)*2048;
    float gi = 0.f, gf = 0.f, gg = 0.f, go = 0.f;
    #pragma unroll
    for (int z = 0; z < 3; z++) {
        const float* gp = g_gpart[z] + base;
        gi += gp[u]; gf += gp[512+u]; gg += gp[1024+u]; go += gp[1536+u];
    }
    gi += bih[u]      + bhh[u];
    gf += bih[512+u]  + bhh[512+u];
    gg += bih[1024+u] + bhh[1024+u];
    go += bih[1536+u] + bhh[1536+u];
    float si = 1.f/(1.f+expf(-gi));
    float sf = 1.f/(1.f+expf(-gf));
    float so = 1.f/(1.f+expf(-go));
    float c = sf * g_c[i] + si * tanhf(gg);
    float h = so * tanhf(c);
    if (dir) {
        float mm = mask[b*Tv + (Tv-1-t)];
        h *= mm; c *= mm;
    }
    g_c[i] = c;
    g_h[(t+1)&1][i] = h;
}

// ---------------- attention key projection GEMM (K-split z=0..1) -----------
__global__ __launch_bounds__(256) void kproj_kernel(int t,
    const float* __restrict__ fattW, const float* __restrict__ battW)
{
    int n0 = blockIdx.x*64, dir = blockIdx.y, z = blockIdx.z;
    const float* W = dir ? battW : fattW;
    const float* h = &g_h[(t+1)&1][dir*BH];
    __shared__ float As[32][17];
    __shared__ float Ws[64][17];
    int tid = threadIdx.x, ty = tid>>4, tx = tid&15;
    float acc[2][4] = {};
    int kbase = z*256;
    for (int k0 = 0; k0 < 256; k0 += 16) {
        for (int i = tid; i < 512; i += 256) {
            int m = i>>4, kc = i&15;
            As[m][kc] = h[m*Hv + kbase + k0 + kc];
        }
        for (int i = tid; i < 1024; i += 256) {
            int r = i>>4, kc = i&15;
            Ws[r][kc] = W[(n0+r)*Hv + kbase + k0 + kc];
        }
        __syncthreads();
        #pragma unroll
        for (int kc = 0; kc < 16; kc++) {
            float a0 = As[ty][kc], a1 = As[ty+16][kc];
            #pragma unroll
            for (int j = 0; j < 4; j++) {
                float w = Ws[tx*4+j][kc];
                acc[0][j] = fmaf(a0, w, acc[0][j]);
                acc[1][j] = fmaf(a1, w, acc[1][j]);
            }
        }
        __syncthreads();
    }
    float* out = g_kpart[z] + dir*Bv*D2v;
    #pragma unroll
    for (int j = 0; j < 4; j++) {
        out[ty*D2v      + n0 + tx*4 + j] = acc[0][j];
        out[(ty+16)*D2v + n0 + tx*4 + j] = acc[1][j];
    }
}

// ---------------- attention: scores, softmax, context; build hcat ----------
__global__ __launch_bounds__(256) void attn_kernel(int t, const float* __restrict__ src,
    const float* __restrict__ fattb, const float* __restrict__ battb)
{
    int b = blockIdx.x, dir = blockIdx.y;
    const float* attb = dir ? battb : fattb;
    __shared__ float ks[1024];
    __shared__ float ws[64];
    __shared__ float red[256];
    int tid = threadIdx.x;
    int kb = (dir*Bv + b)*D2v;
    for (int j = tid; j < 1024; j += 256)
        ks[j] = g_kpart[0][kb+j] + g_kpart[1][kb+j] + attb[j];
    const float* h = &g_h[(t+1)&1][dir*BH + b*Hv];
    float* hcat = &g_hcat[(dir*Bv + b)*1536];
    for (int j = tid; j < 512; j += 256) hcat[j] = h[j];
    __syncthreads();

    const float* srcb = src + (long)b*Sv*D2v;
    {
        int s = tid >> 2, q = tid & 3;
        const float* row = srcb + s*D2v + q*256;
        const float* kq = ks + q*256;
        float p = 0.f;
        #pragma unroll 4
        for (int m = 0; m < 256; m++) p = fmaf(row[m], kq[m], p);
        red[tid] = p;
    }
    __syncthreads();
    if (tid < 64)
        ws[tid] = (red[tid*4]+red[tid*4+1]+red[tid*4+2]+red[tid*4+3]) * ATT_SCALE;
    __syncthreads();
    if (tid < 32) {
        float a = ws[tid], b2 = ws[tid+32];
        float mx = fmaxf(a, b2);
        for (int o = 16; o; o >>= 1) mx = fmaxf(mx, __shfl_xor_sync(0xffffffffu, mx, o));
        float e0 = expf(a - mx), e1 = expf(b2 - mx);
        float sm = e0 + e1;
        for (int o = 16; o; o >>= 1) sm += __shfl_xor_sync(0xffffffffu, sm, o);
        float inv = 1.f / sm;
        ws[tid] = e0 * inv; ws[tid+32] = e1 * inv;
    }
    __syncthreads();
    float ct[4] = {};
    for (int s = 0; s < 64; s++) {
        float p = ws[s];
        const float* row = srcb + s*D2v;
        #pragma unroll
        for (int r = 0; r < 4; r++) ct[r] = fmaf(p, row[r*256+tid], ct[r]);
    }
    #pragma unroll
    for (int r = 0; r < 4; r++) hcat[512 + r*256 + tid] = ct[r];
}

// ---------------- hhat GEMM (K-split z=0..5): [h,ct] @ ahW^T ---------------
// NOTE faithful swap: forward(dir0) uses bah_W, backward(dir1) uses fah_W
__global__ __launch_bounds__(256) void hhatg_kernel(int t,
    const float* __restrict__ W_d0 /*bahW*/, const float* __restrict__ W_d1 /*fahW*/)
{
    int n0 = blockIdx.x*64, dir = blockIdx.y, z = blockIdx.z;
    const float* W = dir ? W_d1 : W_d0;
    const float* A = &g_hcat[dir*Bv*1536];
    __shared__ float As[32][17];
    __shared__ float Ws[64][17];
    int tid = threadIdx.x, ty = tid>>4, tx = tid&15;
    float acc[2][4] = {};
    int kbase = z*256;
    for (int k0 = 0; k0 < 256; k0 += 16) {
        for (int i = tid; i < 512; i += 256) {
            int m = i>>4, kc = i&15;
            As[m][kc] = A[m*1536 + kbase + k0 + kc];
        }
        for (int i = tid; i < 1024; i += 256) {
            int r = i>>4, kc = i&15;
            Ws[r][kc] = W[(n0+r)*1536 + kbase + k0 + kc];
        }
        __syncthreads();
        #pragma unroll
        for (int kc = 0; kc < 16; kc++) {
            float a0 = As[ty][kc], a1 = As[ty+16][kc];
            #pragma unroll
            for (int j = 0; j < 4; j++) {
                float w = Ws[tx*4+j][kc];
                acc[0][j] = fmaf(a0, w, acc[0][j]);
                acc[1][j] = fmaf(a1, w, acc[1][j]);
            }
        }
        __syncthreads();
    }
    float* out = g_hpart[z] + dir*BH;
    #pragma unroll
    for (int j = 0; j < 4; j++) {
        out[ty*Hv      + n0 + tx*4 + j] = acc[0][j];
        out[(ty+16)*Hv + n0 + tx*4 + j] = acc[1][j];
    }
}

// ---------------- hhat finalize: sum partials + bias, tanh, store ----------
__global__ void hhatfin_kernel(int t,
    const float* __restrict__ b_d0 /*bahb*/, const float* __restrict__ b_d1 /*fahb*/)
{
    int i = blockIdx.x*blockDim.x + threadIdx.x;
    if (i >= 2*BH) return;
    int u = i & 511;
    int b = (i >> 9) & 31;
    int dir = i >> 14;
    float s = dir ? b_d1[u] : b_d0[u];
    #pragma unroll
    for (int z = 0; z < 6; z++) s += g_hpart[z][i];
    float v = tanhf(s);
    g_hh[i] = v;
    if (dir == 0) g_outf[(t*Bv + b)*Hv + u] = v;
    else          g_outb[(t*Bv + b)*Hv + u] = v;
}

// ---------------- pack features: [f_out, shifted b_out] -------------------
__global__ void pack_kernel()
{
    int i = blockIdx.x*blockDim.x + threadIdx.x;
    if (i >= Bv*Tv*2*Hv) return;
    int j = i & 1023;
    int bt = i >> 10;
    int b = bt >> 6, t = bt & 63;
    float v;
    if (j < 512) v = g_outf[(t*Bv + b)*Hv + j];
    else         v = (t < Tv-2) ? g_outb[((t+2)*Bv + b)*Hv + (j-512)] : 0.f;
    g_feat[i] = v;
}

// ---------------- tf32 helpers ----------------
__device__ __forceinline__ float f2tf32(float x) {
    uint32_t o;
    asm("cvt.rna.tf32.f32 %0, %1;" : "=r"(o) : "f"(x));
    return __uint_as_float(o);
}

__device__ __forceinline__ void mma_tf32(float& d0, float& d1, float& d2, float& d3,
                                         uint32_t a0, uint32_t a1, uint32_t a2, uint32_t a3,
                                         uint32_t b0, uint32_t b1)
{
    asm volatile(
        "mma.sync.aligned.m16n8k8.row.col.f32.tf32.tf32.f32 "
        "{%0,%1,%2,%3},{%4,%5,%6,%7},{%8,%9},{%0,%1,%2,%3};"
        : "+f"(d0), "+f"(d1), "+f"(d2), "+f"(d3)
        : "r"(a0), "r"(a1), "r"(a2), "r"(a3), "r"(b0), "r"(b1));
}

// ---------------- output projection GEMM (tf32 tensor cores) ---------------
// C[2048, 32000] = feat[2048,1024] @ W^T,  W row-major [32000,1024]
// Block tile 64(M) x 128(N), k-chunk 32. 8 warps: 2(M) x 4(N), warp tile 32x32.
__global__ __launch_bounds__(256) void fc_kernel(
    const float* __restrict__ W, const float* __restrict__ bias, float* __restrict__ out)
{
    __shared__ float As[64][36];   // [m][k], pad 36 -> conflict-free quad access
    __shared__ float Bs[128][36];  // [n][k]

    int n0 = blockIdx.x * 128;
    int m0 = blockIdx.y * 64;
    int tid  = threadIdx.x;
    int warp = tid >> 5, lane = tid & 31;
    int wm = warp >> 2, wn = warp & 3;
    int g  = lane >> 2;      // groupID (0..7)
    int tg = lane & 3;       // threadID in group (0..3)

    float acc[2][4][4];
    #pragma unroll
    for (int i = 0; i < 2; i++)
        #pragma unroll
        for (int j = 0; j < 4; j++)
            #pragma unroll
            for (int q = 0; q < 4; q++) acc[i][j][q] = 0.f;

    for (int k0 = 0; k0 < 1024; k0 += 32) {
        // stage A: 64x32 floats = 512 float4
        #pragma unroll
        for (int l = tid; l < 512; l += 256) {
            int r = l >> 3, kc = (l & 7) * 4;
            float4 v = *(const float4*)&g_feat[(m0 + r) * 1024 + k0 + kc];
            As[r][kc+0] = f2tf32(v.x); As[r][kc+1] = f2tf32(v.y);
            As[r][kc+2] = f2tf32(v.z); As[r][kc+3] = f2tf32(v.w);
        }
        // stage B: 128x32 floats = 1024 float4
        #pragma unroll
        for (int l = tid; l < 1024; l += 256) {
            int r = l >> 3, kc = (l & 7) * 4;
            float4 v = *(const float4*)&W[(long)(n0 + r) * 1024 + k0 + kc];
            Bs[r][kc+0] = f2tf32(v.x); Bs[r][kc+1] = f2tf32(v.y);
            Bs[r][kc+2] = f2tf32(v.z); Bs[r][kc+3] = f2tf32(v.w);
        }
        __syncthreads();

        #pragma unroll
        for (int k8 = 0; k8 < 4; k8++) {
            int kb = k8 * 8;
            uint32_t a[2][4];
            #pragma unroll
            for (int mt = 0; mt < 2; mt++) {
                int rb = wm * 32 + mt * 16;
                a[mt][0] = __float_as_uint(As[rb + g    ][kb + tg    ]);
                a[mt][1] = __float_as_uint(As[rb + g + 8][kb + tg    ]);
                a[mt][2] = __float_as_uint(As[rb + g    ][kb + tg + 4]);
                a[mt][3] = __float_as_uint(As[rb + g + 8][kb + tg + 4]);
            }
            #pragma unroll
            for (int nt = 0; nt < 4; nt++) {
                int nb = wn * 32 + nt * 8 + g;
                uint32_t b0 = __float_as_uint(Bs[nb][kb + tg    ]);
                uint32_t b1 = __float_as_uint(Bs[nb][kb + tg + 4]);
                #pragma unroll
                for (int mt = 0; mt < 2; mt++)
                    mma_tf32(acc[mt][nt][0], acc[mt][nt][1], acc[mt][nt][2], acc[mt][nt][3],
                             a[mt][0], a[mt][1], a[mt][2], a[mt][3], b0, b1);
            }
        }
        __syncthreads();
    }

    // epilogue: d layout -> c0:(g, 2*tg) c1:(g, 2*tg+1) c2:(g+8, 2*tg) c3:(g+8, 2*tg+1)
    #pragma unroll
    for (int mt = 0; mt < 2; mt++) {
        #pragma unroll
        for (int nt = 0; nt < 4; nt++) {
            long m_lo = m0 + wm * 32 + mt * 16 + g;
            long m_hi = m_lo + 8;
            int n = n0 + wn * 32 + nt * 8 + tg * 2;
            out[m_lo * Vv + n    ] = acc[mt][nt][0] + bias[n];
            out[m_lo * Vv + n + 1] = acc[mt][nt][1] + bias[n + 1];
            out[m_hi * Vv + n    ] = acc[mt][nt][2] + bias[n];
            out[m_hi * Vv + n + 1] = acc[mt][nt][3] + bias[n + 1];
        }
    }
}

// ---------------- launch ----------------
extern "C" void kernel_launch(void* const* d_in, const int* in_sizes, int n_in,
                              void* d_out, int out_size)
{
    const float* src   = (const float*)d_in[0];
    const int*   trg   = (const int*)  d_in[1];
    const float* mask  = (const float*)d_in[2];
    const float* emb   = (const float*)d_in[3];
    const float* fWih  = (const float*)d_in[4];
    const float* fWhh  = (const float*)d_in[5];
    const float* fbih  = (const float*)d_in[6];
    const float* fbhh  = (const float*)d_in[7];
    const float* bWih  = (const float*)d_in[8];
    const float* bWhh  = (const float*)d_in[9];
    const float* bbih  = (const float*)d_in[10];
    const float* bbhh  = (const float*)d_in[11];
    const float* fattW = (const float*)d_in[12];
    const float* fattb = (const float*)d_in[13];
    const float* battW = (const float*)d_in[14];
    const float* battb = (const float*)d_in[15];
    const float* fahW  = (const float*)d_in[16];
    const float* fahb  = (const float*)d_in[17];
    const float* bahW  = (const float*)d_in[18];
    const float* bahb  = (const float*)d_in[19];
    const float* fcW   = (const float*)d_in[20];
    const float* fcb   = (const float*)d_in[21];
    const float* feedi = (const float*)d_in[22];
    const float* hidi  = (const float*)d_in[23];
    float* out = (float*)d_out;

    embed_kernel<<<(Bv*Tv*Ev+255)/256, 256>>>(emb, trg);
    init_kernel<<<(2*BH+255)/256, 256>>>(feedi, hidi);
    for (int t = 0; t < Tv; t++) {
        gates_kernel<<<dim3(32,2,3), 256>>>(t, fWih, fWhh, bWih, bWhh);
        lstm_kernel<<<dim3((2*BH+255)/256), 256>>>(t, mask, fbih, fbhh, bbih, bbhh);
        kproj_kernel<<<dim3(16,2,2), 256>>>(t, fattW, battW);
        attn_kernel<<<dim3(Bv,2), 256>>>(t, src, fattb, battb);
        hhatg_kernel<<<dim3(8,2,6), 256>>>(t, bahW, fahW);
        hhatfin_kernel<<<dim3((2*BH+255)/256), 256>>>(t, bahb, fahb);
    }
    pack_kernel<<<(Bv*Tv*2*Hv+255)/256, 256>>>();
    fc_kernel<<<dim3(Vv/128, (Bv*Tv)/64), 256>>>(fcW, fcb, out);
}